// round 9
// baseline (speedup 1.0000x reference)
#include <cuda_runtime.h>

#define Vdim   96
#define Kdim   20
#define Bdim   256
#define Ddim   1024
#define NIJ    9
#define GROUPS 144      // 3*3*4*2*2
#define VK     1920     // Vdim*Kdim

// mega kernel geometry — single wave: 288 + 234 = 522 blocks (< 148*4 resident)
#define BPB    128                 // b's per yphi block
#define SPLITS (Bdim / BPB)        // 2
#define NPHI   (GROUPS * SPLITS)   // 288 yphi-role blocks
#define DCHUNK 40                  // d's per Y block
#define NYB    26                  // ceil(1024/40)
#define NY     (NIJ * NYB)         // 234 Y-role blocks
#define NBLK   (NPHI + NY)         // 522
#define TMEGA  480                 // threads

// ---- scratch (static device globals — no runtime allocation) ----
__device__ float  g_ytr[NIJ * Ddim];    // sum over (e,n,c,v) of Y -> [ij][d]
__device__ float  g_L1[NIJ * VK];       // _T0 + log wt_i + log wr_j per (ij,v,k)
__device__ float  g_W2[GROUPS * Kdim];  // lq - logZ + L3 per (group,k)
__device__ float  g_Wb[NIJ * Bdim];     // sum over (enc,v,k) of yphi -> [ij][b]
__device__ double g_loss;

// ---------------------------------------------------------------------------
// Kernel 1: prep, parallelized over 10 blocks.
//  block 0   : reductions (colsum, Zraw) + W2 (all threads) + zeroing
//  blocks 1-9: g_L1 slab for ij = blk-1 (elementwise, coalesced)
// ---------------------------------------------------------------------------
__global__ __launch_bounds__(1024) void k_prep(
    const float* __restrict__ T0p, const float* __restrict__ tp,
    const float* __restrict__ rp,  const float* __restrict__ ep,
    const float* __restrict__ enp, const float* __restrict__ ecp)
{
    int blk = blockIdx.x, t = threadIdx.x;

    if (blk > 0) {
        // ---- L1 slab for one ij ----
        int ij = blk - 1;
        int i = ij / 3, j = ij % 3;
        for (int idx = t; idx < VK; idx += 1024) {
            float t0 = T0p[idx];
            float lwt = 0.f, lwr = 0.f;
            if (i < 2) {
                float s = 1.f / (1.f + __expf(-tp[idx]));
                lwt = __logf((i == 0) ? s : 1.f - s);
            }
            if (j < 2) {
                float s = 1.f / (1.f + __expf(-rp[idx]));
                lwr = __logf((j == 0) ? s : 1.f - s);
            }
            g_L1[ij * VK + idx] = t0 + lwt + lwr;
        }
        return;
    }

    // ---- block 0: reductions + W2 ----
    __shared__ float se[VK], st[VK], sr[VK];
    __shared__ float scolsum[Kdim];
    __shared__ float sZraw[NIJ * Kdim];
    __shared__ float slz[NIJ * Kdim];
    __shared__ float slpe[4 * Kdim], slpn[2 * Kdim], slpc[2 * Kdim];
    int lane = t & 31, w = t >> 5;

    for (int i = t; i < NIJ * Bdim; i += 1024) g_Wb[i] = 0.f;
    if (t == 0) g_loss = 0.0;

    for (int i = t; i < VK; i += 1024) {
        se[i] = __expf(T0p[i]);
        st[i] = 1.f / (1.f + __expf(-tp[i]));
        sr[i] = 1.f / (1.f + __expf(-rp[i]));
    }
    __syncthreads();

    // column sums of eT0 over V (warp per column)
    if (w < Kdim) {
        float s = 0.f;
        for (int v = lane; v < Vdim; v += 32) s += se[v * Kdim + w];
#pragma unroll
        for (int off = 16; off; off >>= 1) s += __shfl_down_sync(0xffffffffu, s, off);
        if (lane == 0) scolsum[w] = s;
    }
    // raw Z[ij][k] (warp per output)
    for (int o = w; o < NIJ * Kdim; o += 32) {
        int ij = o / Kdim, k = o - ij * Kdim, i = ij / 3, j = ij % 3;
        float s = 0.f;
        for (int v = lane; v < Vdim; v += 32) {
            int r = v * Kdim + k;
            float wt = (i == 0) ? st[r] : (i == 1) ? 1.f - st[r] : 1.f;
            float wr = (j == 0) ? sr[r] : (j == 1) ? 1.f - sr[r] : 1.f;
            s += se[r] * wt * wr;
        }
#pragma unroll
        for (int off = 16; off; off >>= 1) s += __shfl_down_sync(0xffffffffu, s, off);
        if (lane == 0) sZraw[o] = s;
    }
    __syncthreads();

    // log-softmax tables (20 threads, trivial)
    if (t < Kdim) {
        float s, l;
        s = 0.f; for (int e = 0; e < 4; ++e) s += __expf(ep[e * Kdim + t]);
        l = __logf(s);
        for (int e = 0; e < 4; ++e) slpe[e * Kdim + t] = ep[e * Kdim + t] - l;
        s = 0.f; for (int n = 0; n < 2; ++n) s += __expf(enp[n * Kdim + t]);
        l = __logf(s);
        for (int n = 0; n < 2; ++n) slpn[n * Kdim + t] = enp[n * Kdim + t] - l;
        s = 0.f; for (int c = 0; c < 2; ++c) s += __expf(ecp[c * Kdim + t]);
        l = __logf(s);
        for (int c = 0; c < 2; ++c) slpc[c * Kdim + t] = ecp[c * Kdim + t] - l;
    }
    // lz[ij][k] = lqt_i + lqr_j - log Zraw[ij][k]  (180 threads)
    if (t < NIJ * Kdim) {
        int ij = t / Kdim, k = t - ij * Kdim;
        int i = ij / 3, j = ij % 3;
        float inv = 1.f / scolsum[k];
        float pt = sZraw[2 * Kdim + k] * inv;   // ij=(0,2): wt=lt, wr=1
        float pr = sZraw[6 * Kdim + k] * inv;   // ij=(2,0): wt=1, wr=lr
        float lqt = (i == 0) ? __logf(pt) : (i == 1) ? __logf(1.f - pt) : 0.f;
        float lqr = (j == 0) ? __logf(pr) : (j == 1) ? __logf(1.f - pr) : 0.f;
        slz[t] = lqt + lqr - __logf(sZraw[t]);
    }
    __syncthreads();

    // W2 written by ALL threads (2880 outputs, 3 strided iterations)
    for (int idx = t; idx < GROUPS * Kdim; idx += 1024) {
        int g = idx / Kdim, k = idx - g * Kdim;
        int ij = g >> 4, enc = g & 15;
        g_W2[idx] = slz[ij * Kdim + k] + slpe[(enc >> 2) * Kdim + k]
                  + slpn[((enc >> 1) & 1) * Kdim + k] + slpc[(enc & 1) * Kdim + k];
    }
}

// ---------------------------------------------------------------------------
// Kernel 2 (MEGA): streams yphi (283MB) + Y (56.6MB) in ONE resident wave.
// Pure streaming — no fences, no counters.
// ---------------------------------------------------------------------------
__global__ __launch_bounds__(TMEGA) void k_mega(
    const float* __restrict__ yphi, const float* __restrict__ Yv)
{
    int blk = blockIdx.x, t = threadIdx.x;
    int lane = t & 31, w = t >> 5;

    if (blk < NPHI) {
        __shared__ float  sW[Kdim];
        __shared__ float  swb[BPB * 16];       // [b][warp], 15 warps pad 16
        __shared__ double sred[TMEGA / 32];

        int group  = blk / SPLITS;             // ij*16 + enc
        int bsplit = blk - group * SPLITS;
        int ij = group >> 4;

        if (t < Kdim) sW[t] = g_W2[group * Kdim + t];
        __syncthreads();

        // per-thread weights: one load, four smem adds — no MUFU
        float4 wv = *(const float4*)(g_L1 + ij * VK + 4 * t);
        int kb = (4 * t) % Kdim;               // 4|20: never wraps inside a float4
        wv.x += sW[kb]; wv.y += sW[kb + 1]; wv.z += sW[kb + 2]; wv.w += sW[kb + 3];

        const float4* p = (const float4*)(yphi + (size_t)group * (Bdim * VK)
                                               + (size_t)bsplit * BPB * VK) + t;
        float acc = 0.f;
#pragma unroll 8
        for (int b = 0; b < BPB; ++b) {
            float4 x = p[(size_t)b * (VK / 4)];
            acc += x.x * wv.x; acc += x.y * wv.y;
            acc += x.z * wv.z; acc += x.w * wv.w;
            float s = (x.x + x.y) + (x.z + x.w);
#pragma unroll
            for (int off = 16; off; off >>= 1) s += __shfl_down_sync(0xffffffffu, s, off);
            if (lane == 0) swb[b * 16 + w] = s;
        }
        __syncthreads();
        // Wb: BPB=128 outputs, threads 0..127
        if (t < BPB) {
            float s = 0.f;
#pragma unroll
            for (int w2 = 0; w2 < TMEGA / 32; ++w2) s += swb[t * 16 + w2];
            atomicAdd(&g_Wb[ij * Bdim + bsplit * BPB + t], s);
        }
#pragma unroll
        for (int off = 16; off; off >>= 1) acc += __shfl_down_sync(0xffffffffu, acc, off);
        if (lane == 0) sred[w] = (double)acc;
        __syncthreads();
        if (t == 0) {
            double s = 0.0;
#pragma unroll
            for (int w2 = 0; w2 < TMEGA / 32; ++w2) s += sred[w2];
            atomicAdd(&g_loss, s);
        }
    } else {
        // ---- Y reduction role: 40 d's x 12 threads, each covers 2 float4 cols
        __shared__ float sY[TMEGA];
        int yb    = blk - NPHI;
        int ij    = yb / NYB;
        int chunk = yb - ij * NYB;
        int d0 = chunk * DCHUNK;
        int dl = t / 12, vq = t - dl * 12;     // dl: 0..39, vq: 0..11
        int d  = d0 + dl;
        float s = 0.f;
        if (d < Ddim) {
            const float4* q = (const float4*)Yv
                + (size_t)ij * (16 * Ddim * 24) + (size_t)d * 24 + vq;
#pragma unroll
            for (int enc = 0; enc < 16; ++enc) {
                float4 x0 = q[(size_t)enc * (Ddim * 24)];
                float4 x1 = q[(size_t)enc * (Ddim * 24) + 12];
                s += (x0.x + x0.y) + (x0.z + x0.w);
                s += (x1.x + x1.y) + (x1.z + x1.w);
            }
        }
        sY[t] = s;
        __syncthreads();
        if (t < DCHUNK && d0 + t < Ddim) {
            float r = 0.f;
#pragma unroll
            for (int v = 0; v < 12; ++v) r += sY[t * 12 + v];
            g_ytr[ij * Ddim + d0 + t] = r;
        }
    }
}

// ---------------------------------------------------------------------------
// Kernel 3: finisher — missing-rate logs + Wb dot + final scale (1 block)
// ---------------------------------------------------------------------------
__global__ __launch_bounds__(256) void k_finish(
    const int* __restrict__ index, float* __restrict__ out)
{
    __shared__ double sred[256];
    int t = threadIdx.x;
    int d = index[t];
    float y[9];
#pragma unroll
    for (int ij = 0; ij < 9; ++ij) y[ij] = g_ytr[ij * Ddim + d];
    float tot = ((y[0] + y[1]) + (y[2] + y[3]))
              + ((y[4] + y[5]) + (y[6] + y[7])) + y[8];
    float inv = 1.f / tot;
    float lmr[4];
    lmr[0] = __logf((y[0] + y[1] + y[3] + y[4]) * inv);  // m00
    lmr[1] = __logf((y[2] + y[5]) * inv);                // m01
    lmr[2] = __logf((y[6] + y[7]) * inv);                // m10
    lmr[3] = __logf(y[8] * inv);                         // m11
    double acc = 0.0;
#pragma unroll
    for (int ij = 0; ij < 9; ++ij) {
        int i = ij / 3, j = ij % 3;
        int sel = ((i == 2) ? 2 : 0) + ((j == 2) ? 1 : 0);
        acc += (double)g_Wb[ij * Bdim + t] * (double)lmr[sel];
    }
    sred[t] = acc;
    __syncthreads();
    for (int off = 128; off; off >>= 1) {
        if (t < off) sred[t] += sred[t + off];
        __syncthreads();
    }
    if (t == 0) out[0] = (float)(-(g_loss + sred[0]) / (double)VK);
}

// ---------------------------------------------------------------------------
extern "C" void kernel_launch(void* const* d_in, const int* in_sizes, int n_in,
                              void* d_out, int out_size) {
    (void)in_sizes; (void)n_in; (void)out_size;
    const float* yphi = (const float*)d_in[0];
    const float* Yv   = (const float*)d_in[1];
    const float* T0p  = (const float*)d_in[2];
    const float* tp   = (const float*)d_in[3];
    const float* rp   = (const float*)d_in[4];
    const float* ep   = (const float*)d_in[5];
    const float* enp  = (const float*)d_in[6];
    const float* ecp  = (const float*)d_in[7];
    const int*   idx  = (const int*)d_in[8];
    float* out = (float*)d_out;

    k_prep<<<10, 1024>>>(T0p, tp, rp, ep, enp, ecp);
    k_mega<<<NBLK, TMEGA>>>(yphi, Yv);
    k_finish<<<1, 256>>>(idx, out);
}

// round 10
// speedup vs baseline: 1.0862x; 1.0862x over previous
#include <cuda_runtime.h>

#define Vdim   96
#define Kdim   20
#define Bdim   256
#define Ddim   1024
#define NIJ    9
#define GROUPS 144      // 3*3*4*2*2
#define VK     1920     // Vdim*Kdim

// mega kernel geometry — R5/R8-proven: fine-grained, balances across SMs
#define BPB    64                  // b's per yphi block
#define SPLITS (Bdim / BPB)        // 4
#define NPHI   (GROUPS * SPLITS)   // 576 yphi-role blocks
#define DCHUNK 20                  // d's per Y block
#define NYB    52                  // ceil(1024/20)
#define NY     (NIJ * NYB)         // 468 Y-role blocks
#define NBLK   (NPHI + NY)         // 1044
#define TMEGA  480                 // threads

// ---- scratch (static device globals — no runtime allocation) ----
__device__ float  g_ytr[NIJ * Ddim];    // sum over (e,n,c,v) of Y -> [ij][d]
__device__ float  g_L1[NIJ * VK];       // _T0 + log wt_i + log wr_j per (ij,v,k)
__device__ float  g_W2[GROUPS * Kdim];  // lq - logZ + L3 per (group,k)
__device__ float  g_Wb[NIJ * Bdim];     // sum over (enc,v,k) of yphi -> [ij][b]
__device__ double g_loss;

// ---------------------------------------------------------------------------
// Kernel 1: prep (10 blocks). Block 0: reductions + W2 with ALL params staged
// into smem first (no serial dependent global loads). Blocks 1-9: L1 slabs.
// ---------------------------------------------------------------------------
__global__ __launch_bounds__(1024) void k_prep(
    const float* __restrict__ T0p, const float* __restrict__ tp,
    const float* __restrict__ rp,  const float* __restrict__ ep,
    const float* __restrict__ enp, const float* __restrict__ ecp)
{
    int blk = blockIdx.x, t = threadIdx.x;

    if (blk > 0) {
        // ---- L1 slab for one ij: _T0 + log wt_i + log wr_j ----
        int ij = blk - 1;
        int i = ij / 3, j = ij % 3;
        for (int idx = t; idx < VK; idx += 1024) {
            float t0 = T0p[idx];
            float lwt = 0.f, lwr = 0.f;
            if (i < 2) {
                float s = 1.f / (1.f + __expf(-tp[idx]));
                lwt = __logf((i == 0) ? s : 1.f - s);
            }
            if (j < 2) {
                float s = 1.f / (1.f + __expf(-rp[idx]));
                lwr = __logf((j == 0) ? s : 1.f - s);
            }
            g_L1[ij * VK + idx] = t0 + lwt + lwr;
        }
        return;
    }

    // ---- block 0: reductions + W2 ----
    __shared__ float se[VK], st[VK], sr[VK];
    __shared__ float sprm[8 * Kdim];          // ep(4) | enp(2) | ecp(2), packed
    __shared__ float scolsum[Kdim];
    __shared__ float sZraw[NIJ * Kdim];
    __shared__ float slz[NIJ * Kdim];
    __shared__ float slpe[4 * Kdim], slpn[2 * Kdim], slpc[2 * Kdim];
    int lane = t & 31, w = t >> 5;

    // phase 1: one parallel, coalesced load round for everything
    if (t < 8 * Kdim)
        sprm[t] = (t < 4 * Kdim) ? ep[t]
                : (t < 6 * Kdim) ? enp[t - 4 * Kdim]
                                 : ecp[t - 6 * Kdim];
    for (int i = t; i < VK; i += 1024) {
        se[i] = __expf(T0p[i]);
        st[i] = 1.f / (1.f + __expf(-tp[i]));
        sr[i] = 1.f / (1.f + __expf(-rp[i]));
    }
    for (int i = t; i < NIJ * Bdim; i += 1024) g_Wb[i] = 0.f;
    if (t == 0) g_loss = 0.0;
    __syncthreads();

    // phase 2: colsum (warp per k) and Zraw (warp per output), all from smem
    if (w < Kdim) {
        float s = 0.f;
        for (int v = lane; v < Vdim; v += 32) s += se[v * Kdim + w];
#pragma unroll
        for (int off = 16; off; off >>= 1) s += __shfl_down_sync(0xffffffffu, s, off);
        if (lane == 0) scolsum[w] = s;
    }
    for (int o = w; o < NIJ * Kdim; o += 32) {
        int ij = o / Kdim, k = o - ij * Kdim, i = ij / 3, j = ij % 3;
        float s = 0.f;
        for (int v = lane; v < Vdim; v += 32) {
            int r = v * Kdim + k;
            float wt = (i == 0) ? st[r] : (i == 1) ? 1.f - st[r] : 1.f;
            float wr = (j == 0) ? sr[r] : (j == 1) ? 1.f - sr[r] : 1.f;
            s += se[r] * wt * wr;
        }
#pragma unroll
        for (int off = 16; off; off >>= 1) s += __shfl_down_sync(0xffffffffu, s, off);
        if (lane == 0) sZraw[o] = s;
    }
    __syncthreads();

    // phase 3: small log tables — all operands in smem
    if (t < Kdim) {
        float s, l;
        s = 0.f; for (int e = 0; e < 4; ++e) s += __expf(sprm[e * Kdim + t]);
        l = __logf(s);
        for (int e = 0; e < 4; ++e) slpe[e * Kdim + t] = sprm[e * Kdim + t] - l;
        s = 0.f; for (int n = 0; n < 2; ++n) s += __expf(sprm[(4 + n) * Kdim + t]);
        l = __logf(s);
        for (int n = 0; n < 2; ++n) slpn[n * Kdim + t] = sprm[(4 + n) * Kdim + t] - l;
        s = 0.f; for (int c = 0; c < 2; ++c) s += __expf(sprm[(6 + c) * Kdim + t]);
        l = __logf(s);
        for (int c = 0; c < 2; ++c) slpc[c * Kdim + t] = sprm[(6 + c) * Kdim + t] - l;
    }
    if (t < NIJ * Kdim) {
        int ij = t / Kdim, k = t - ij * Kdim;
        int i = ij / 3, j = ij % 3;
        float inv = 1.f / scolsum[k];
        float pt = sZraw[2 * Kdim + k] * inv;   // ij=(0,2): wt=lt, wr=1
        float pr = sZraw[6 * Kdim + k] * inv;   // ij=(2,0): wt=1, wr=lr
        float lqt = (i == 0) ? __logf(pt) : (i == 1) ? __logf(1.f - pt) : 0.f;
        float lqr = (j == 0) ? __logf(pr) : (j == 1) ? __logf(1.f - pr) : 0.f;
        slz[t] = lqt + lqr - __logf(sZraw[t]);
    }
    __syncthreads();

    // phase 4: W2 written by all threads (2880 outputs, 3 strided iterations)
    for (int idx = t; idx < GROUPS * Kdim; idx += 1024) {
        int g = idx / Kdim, k = idx - g * Kdim;
        int ij = g >> 4, enc = g & 15;
        g_W2[idx] = slz[ij * Kdim + k] + slpe[(enc >> 2) * Kdim + k]
                  + slpn[((enc >> 1) & 1) * Kdim + k] + slpc[(enc & 1) * Kdim + k];
    }
}

// ---------------------------------------------------------------------------
// Kernel 2 (MEGA): streams yphi (283MB) + Y (56.6MB); R8-proven structure,
// unchanged: no fences, no counters, fine-grained blocks.
// ---------------------------------------------------------------------------
__global__ __launch_bounds__(TMEGA) void k_mega(
    const float* __restrict__ yphi, const float* __restrict__ Yv)
{
    int blk = blockIdx.x, t = threadIdx.x;
    int lane = t & 31, w = t >> 5;

    if (blk < NPHI) {
        __shared__ float  sW[Kdim];
        __shared__ float  swb[BPB * 16];       // [b][warp], 15 warps pad 16
        __shared__ double sred[TMEGA / 32];

        int group  = blk / SPLITS;             // ij*16 + enc
        int bsplit = blk - group * SPLITS;
        int ij = group >> 4;

        if (t < Kdim) sW[t] = g_W2[group * Kdim + t];
        __syncthreads();

        // per-thread weights: one load, four smem adds — no MUFU
        float4 wv = *(const float4*)(g_L1 + ij * VK + 4 * t);
        int kb = (4 * t) % Kdim;               // 4|20: never wraps inside a float4
        wv.x += sW[kb]; wv.y += sW[kb + 1]; wv.z += sW[kb + 2]; wv.w += sW[kb + 3];

        const float4* p = (const float4*)(yphi + (size_t)group * (Bdim * VK)
                                               + (size_t)bsplit * BPB * VK) + t;
        float acc = 0.f;
#pragma unroll 8
        for (int b = 0; b < BPB; ++b) {
            float4 x = p[(size_t)b * (VK / 4)];
            acc += x.x * wv.x; acc += x.y * wv.y;
            acc += x.z * wv.z; acc += x.w * wv.w;
            float s = (x.x + x.y) + (x.z + x.w);
#pragma unroll
            for (int off = 16; off; off >>= 1) s += __shfl_down_sync(0xffffffffu, s, off);
            if (lane == 0) swb[b * 16 + w] = s;
        }
        __syncthreads();
        if (t < BPB) {
            float s = 0.f;
#pragma unroll
            for (int w2 = 0; w2 < TMEGA / 32; ++w2) s += swb[t * 16 + w2];
            atomicAdd(&g_Wb[ij * Bdim + bsplit * BPB + t], s);
        }
#pragma unroll
        for (int off = 16; off; off >>= 1) acc += __shfl_down_sync(0xffffffffu, acc, off);
        if (lane == 0) sred[w] = (double)acc;
        __syncthreads();
        if (t == 0) {
            double s = 0.0;
#pragma unroll
            for (int w2 = 0; w2 < TMEGA / 32; ++w2) s += sred[w2];
            atomicAdd(&g_loss, s);
        }
    } else {
        // ---- Y reduction role: 20 d's x 24 float4 threads ----
        __shared__ float sY[TMEGA];
        int yb    = blk - NPHI;
        int ij    = yb / NYB;
        int chunk = yb - ij * NYB;
        int d0 = chunk * DCHUNK;
        int dl = t / 24, vq = t - dl * 24;
        int d  = d0 + dl;
        float s = 0.f;
        if (d < Ddim) {
            const float4* q = (const float4*)Yv
                + (size_t)ij * (16 * Ddim * 24) + (size_t)d * 24 + vq;
#pragma unroll
            for (int enc = 0; enc < 16; ++enc) {
                float4 x = q[(size_t)enc * (Ddim * 24)];
                s += (x.x + x.y) + (x.z + x.w);
            }
        }
        sY[t] = s;
        __syncthreads();
        if (t < DCHUNK && d0 + t < Ddim) {
            float r = 0.f;
#pragma unroll
            for (int v = 0; v < 24; ++v) r += sY[t * 24 + v];
            g_ytr[ij * Ddim + d0 + t] = r;
        }
    }
}

// ---------------------------------------------------------------------------
// Kernel 3: finisher — Wb loads issued early, then lmr logs + dot (1 block)
// ---------------------------------------------------------------------------
__global__ __launch_bounds__(256) void k_finish(
    const int* __restrict__ index, float* __restrict__ out)
{
    __shared__ double sred[256];
    int t = threadIdx.x;
    // issue independent Wb loads FIRST so they overlap the index->ytr chain
    float wb[9];
#pragma unroll
    for (int ij = 0; ij < 9; ++ij) wb[ij] = g_Wb[ij * Bdim + t];
    int d = index[t];
    float y[9];
#pragma unroll
    for (int ij = 0; ij < 9; ++ij) y[ij] = g_ytr[ij * Ddim + d];
    float tot = ((y[0] + y[1]) + (y[2] + y[3]))
              + ((y[4] + y[5]) + (y[6] + y[7])) + y[8];
    float inv = 1.f / tot;
    float lmr[4];
    lmr[0] = __logf((y[0] + y[1] + y[3] + y[4]) * inv);  // m00
    lmr[1] = __logf((y[2] + y[5]) * inv);                // m01
    lmr[2] = __logf((y[6] + y[7]) * inv);                // m10
    lmr[3] = __logf(y[8] * inv);                         // m11
    double acc = 0.0;
#pragma unroll
    for (int ij = 0; ij < 9; ++ij) {
        int i = ij / 3, j = ij % 3;
        int sel = ((i == 2) ? 2 : 0) + ((j == 2) ? 1 : 0);
        acc += (double)wb[ij] * (double)lmr[sel];
    }
    sred[t] = acc;
    __syncthreads();
    for (int off = 128; off; off >>= 1) {
        if (t < off) sred[t] += sred[t + off];
        __syncthreads();
    }
    if (t == 0) out[0] = (float)(-(g_loss + sred[0]) / (double)VK);
}

// ---------------------------------------------------------------------------
extern "C" void kernel_launch(void* const* d_in, const int* in_sizes, int n_in,
                              void* d_out, int out_size) {
    (void)in_sizes; (void)n_in; (void)out_size;
    const float* yphi = (const float*)d_in[0];
    const float* Yv   = (const float*)d_in[1];
    const float* T0p  = (const float*)d_in[2];
    const float* tp   = (const float*)d_in[3];
    const float* rp   = (const float*)d_in[4];
    const float* ep   = (const float*)d_in[5];
    const float* enp  = (const float*)d_in[6];
    const float* ecp  = (const float*)d_in[7];
    const int*   idx  = (const int*)d_in[8];
    float* out = (float*)d_out;

    k_prep<<<10, 1024>>>(T0p, tp, rp, ep, enp, ecp);
    k_mega<<<NBLK, TMEGA>>>(yphi, Yv);
    k_finish<<<1, 256>>>(idx, out);
}